// round 3
// baseline (speedup 1.0000x reference)
#include <cuda_runtime.h>
#include <math.h>

#define Lc   256
#define Bc   128
#define Dc   512
#define Hc   512
#define G3c  1536      // 3*H
#define OUT2H 1024     // 2*H

// Scratch (static __device__ — no allocation).
// g_xg[pass][node][b][3H] : precomputed x-side gate preactivations (+bias)
__device__ float g_xg[(size_t)2 * Lc * Bc * G3c];      // ~403 MB
// g_hsum[b][node][H] : bottom-up child-sum accumulator
__device__ float g_hsum[(size_t)Bc * Lc * Hc];         // ~67 MB

// ---------------------------------------------------------------------------
// Zero the child-sum accumulator (must happen every launch: it accumulates).
// ---------------------------------------------------------------------------
__global__ __launch_bounds__(256) void zero_hsum_kernel() {
    size_t i = ((size_t)blockIdx.x * 256 + threadIdx.x) * 4;
    float4 z = make_float4(0.f, 0.f, 0.f, 0.f);
    *(float4*)&g_hsum[i] = z;
}

// ---------------------------------------------------------------------------
// Precompute XG = emb @ Wx + b for both passes.
// A = emb viewed as [L*B, D] row-major (row = node*B + b), B = Wx [D, 3H].
// 128x128x16 tiles, 256 threads, 8x8 microtiles.
// grid: (12, 256, 2)
// ---------------------------------------------------------------------------
__global__ __launch_bounds__(256) void xg_gemm(
    const float* __restrict__ emb,
    const float* __restrict__ Wx0, const float* __restrict__ bias0,
    const float* __restrict__ Wx1, const float* __restrict__ bias1)
{
    const int pass = blockIdx.z;
    const float* __restrict__ Wx   = pass ? Wx1   : Wx0;
    const float* __restrict__ bias = pass ? bias1 : bias0;
    float* C = g_xg + (size_t)pass * Lc * Bc * G3c;

    __shared__ __align__(16) float As[16][128];
    __shared__ __align__(16) float Bs[16][128];

    const int m0 = blockIdx.y * 128;
    const int n0 = blockIdx.x * 128;
    const int tid = threadIdx.x;
    const int tr = tid >> 4;
    const int tc = tid & 15;

    float acc[8][8];
#pragma unroll
    for (int i = 0; i < 8; i++)
#pragma unroll
        for (int j = 0; j < 8; j++) acc[i][j] = 0.f;

    for (int kt = 0; kt < Dc; kt += 16) {
#pragma unroll
        for (int l = 0; l < 2; l++) {
            int f = tid + l * 256;           // 0..511 float4 slots
            int row = f >> 2;                // 0..127
            int c4 = (f & 3) << 2;           // 0,4,8,12
            float4 v = *(const float4*)&emb[(size_t)(m0 + row) * Dc + kt + c4];
            As[c4 + 0][row] = v.x;
            As[c4 + 1][row] = v.y;
            As[c4 + 2][row] = v.z;
            As[c4 + 3][row] = v.w;
        }
#pragma unroll
        for (int l = 0; l < 2; l++) {
            int f = tid + l * 256;
            int row = f >> 5;                // 0..15
            int c4 = (f & 31) << 2;          // 0..124
            *(float4*)&Bs[row][c4] =
                *(const float4*)&Wx[(size_t)(kt + row) * G3c + n0 + c4];
        }
        __syncthreads();
#pragma unroll
        for (int k = 0; k < 16; k++) {
            float a[8], b[8];
            *(float4*)&a[0] = *(const float4*)&As[k][tr * 8];
            *(float4*)&a[4] = *(const float4*)&As[k][tr * 8 + 4];
            *(float4*)&b[0] = *(const float4*)&Bs[k][tc * 8];
            *(float4*)&b[4] = *(const float4*)&Bs[k][tc * 8 + 4];
#pragma unroll
            for (int i = 0; i < 8; i++)
#pragma unroll
                for (int j = 0; j < 8; j++)
                    acc[i][j] += a[i] * b[j];
        }
        __syncthreads();
    }

#pragma unroll
    for (int i = 0; i < 8; i++) {
        int row = m0 + tr * 8 + i;
#pragma unroll
        for (int j = 0; j < 8; j += 4) {
            int col = n0 + tc * 8 + j;
            float4 v;
            v.x = acc[i][j + 0] + bias[col + 0];
            v.y = acc[i][j + 1] + bias[col + 1];
            v.z = acc[i][j + 2] + bias[col + 2];
            v.w = acc[i][j + 3] + bias[col + 3];
            *(float4*)&C[(size_t)row * G3c + col] = v;
        }
    }
}

// ---------------------------------------------------------------------------
// One recurrence step (both passes). grid (8 colTiles, 8 bTiles, 2 passes),
// 256 threads = 4 k-groups x 64. Tile: 16 batch rows x 64 h-cols x 3 gates.
// Each thread: 4x4x3 accumulators over its 128-wide K slice; smem reduction;
// fused GRU epilogue; DT scatter-add of hn into parent's hsum row.
// ---------------------------------------------------------------------------
__global__ __launch_bounds__(256) void step_kernel(
    const int t,
    const int* __restrict__ indexes,     // [L][B] node order for DT
    const int* __restrict__ td_node,     // [L][B]
    const int* __restrict__ pidx,        // [L][B] parent index per node
    const float* __restrict__ pvalid,    // [L][B] 0 at root
    const float* __restrict__ Uh0,       // dt_Uh [H][3H]
    const float* __restrict__ Uh1,       // td_Uh
    float* out)                          // [B][L][2H] (+ root tail)
{
    const int pass = blockIdx.z;
    const int b0 = blockIdx.y * 16;
    const int j0 = blockIdx.x * 64;
    const float* __restrict__ Uh = pass ? Uh1 : Uh0;

    __shared__ __align__(16) float sh[4][8][16];    // [kg][k][bb]
    __shared__ __align__(16) float sU[4][8][192];   // [kg][k][gate*64+jj]
    __shared__ float sred[64][49];                  // padded (bank-safe)
    __shared__ int   sNode[16];
    __shared__ int   sBase[16];
    __shared__ float sScale[16];

    const int tid = threadIdx.x;
    const int kg = tid >> 6;
    const int lt = tid & 63;

    if (tid < 16) {
        int b = b0 + tid;
        int node = pass ? td_node[t * Bc + b] : indexes[t * Bc + b];
        sNode[tid] = node;
        if (pass) {
            int p = pidx[node * Bc + b];
            sBase[tid] = (b * Lc + p) * OUT2H + Hc;  // parent Htd row in out
            sScale[tid] = pvalid[node * Bc + b];     // 0 at root masks garbage
        } else {
            sBase[tid] = (b * Lc + node) * Hc;       // child-sum row in g_hsum
            sScale[tid] = 1.0f;
        }
    }
    __syncthreads();

    const float* hsrc = pass ? (const float*)out : (const float*)g_hsum;

    float acc[4][4][3];
#pragma unroll
    for (int i = 0; i < 4; i++)
#pragma unroll
        for (int j = 0; j < 4; j++)
#pragma unroll
            for (int g = 0; g < 3; g++) acc[i][j][g] = 0.f;

    const int r0 = (lt >> 4) << 2;   // 0,4,8,12 (batch rows)
    const int c0 = (lt & 15) << 2;   // 0..60    (h cols)
    const int kbase = kg << 7;       // 128 K per group

    for (int ck = 0; ck < 16; ck++) {
        const int k0 = kbase + (ck << 3);
        // h chunk: 8k x 16b = 128 values, 2 per thread (gathered rows)
#pragma unroll
        for (int i = 0; i < 2; i++) {
            int idx = lt + (i << 6);
            int kk = idx >> 4;
            int bb = idx & 15;
            sh[kg][kk][bb] = hsrc[sBase[bb] + k0 + kk] * sScale[bb];
        }
        // U chunk: 8k x (3 gates x 64 cols) = 384 float4, 6 per thread
#pragma unroll
        for (int i = 0; i < 6; i++) {
            int v = lt + (i << 6);
            int kk = v / 48;
            int rem = v - kk * 48;
            int g = rem >> 4;
            int jj = (rem & 15) << 2;
            *(float4*)&sU[kg][kk][g * 64 + jj] =
                *(const float4*)&Uh[(size_t)(k0 + kk) * G3c + g * Hc + j0 + jj];
        }
        __syncthreads();
#pragma unroll
        for (int kk = 0; kk < 8; kk++) {
            float4 a4 = *(const float4*)&sh[kg][kk][r0];
            float4 u0 = *(const float4*)&sU[kg][kk][c0];
            float4 u1 = *(const float4*)&sU[kg][kk][64 + c0];
            float4 u2 = *(const float4*)&sU[kg][kk][128 + c0];
            const float av[4]  = {a4.x, a4.y, a4.z, a4.w};
            const float u0v[4] = {u0.x, u0.y, u0.z, u0.w};
            const float u1v[4] = {u1.x, u1.y, u1.z, u1.w};
            const float u2v[4] = {u2.x, u2.y, u2.z, u2.w};
#pragma unroll
            for (int i = 0; i < 4; i++)
#pragma unroll
                for (int j = 0; j < 4; j++) {
                    acc[i][j][0] += av[i] * u0v[j];
                    acc[i][j][1] += av[i] * u1v[j];
                    acc[i][j][2] += av[i] * u2v[j];
                }
        }
        __syncthreads();
    }

    // split-K reduction across the 4 k-groups
    if (kg == 0) {
#pragma unroll
        for (int i = 0; i < 4; i++)
#pragma unroll
            for (int j = 0; j < 4; j++)
#pragma unroll
                for (int g = 0; g < 3; g++)
                    sred[lt][(i * 4 + j) * 3 + g] = acc[i][j][g];
    }
    __syncthreads();
    for (int gg = 1; gg < 4; gg++) {
        if (kg == gg) {
#pragma unroll
            for (int i = 0; i < 4; i++)
#pragma unroll
                for (int j = 0; j < 4; j++)
#pragma unroll
                    for (int g = 0; g < 3; g++)
                        sred[lt][(i * 4 + j) * 3 + g] += acc[i][j][g];
        }
        __syncthreads();
    }

    // fused GRU epilogue (group 0: 64 threads x 16 outputs each)
    if (kg == 0) {
#pragma unroll
        for (int i = 0; i < 4; i++) {
            const int bb = r0 + i;
            const int b = b0 + bb;
            const int node = sNode[bb];
            const float* xrow =
                g_xg + (((size_t)pass * Lc + node) * Bc + b) * G3c;
            const float hscale = sScale[bb];
            const int hbase = sBase[bb];
            int par = 0; float pv = 0.f;
            if (pass == 0) {
                par = pidx[node * Bc + b];
                pv = pvalid[node * Bc + b];
            }
#pragma unroll
            for (int jj = 0; jj < 4; jj++) {
                const int j = j0 + c0 + jj;
                const int s = (i * 4 + jj) * 3;
                float hr = sred[lt][s + 0];
                float hz = sred[lt][s + 1];
                float hg = sred[lt][s + 2];
                float xr = xrow[j];
                float xz = xrow[Hc + j];
                float xn = xrow[2 * Hc + j];
                float hp = hsrc[hbase + j] * hscale;
                float r = 1.f / (1.f + expf(-(xr + hr)));
                float z = 1.f / (1.f + expf(-(xz + hz)));
                float nn = tanhf(xn + r * hg);
                float hnew = (1.f - z) * nn + z * hp;
                out[((size_t)b * Lc + node) * OUT2H + pass * Hc + j] = hnew;
                // bottom-up: contribute to parent's child-sum (unique (b,j)
                // per thread this step -> race-free plain RMW)
                if (pass == 0 && pv != 0.f) {
                    g_hsum[((size_t)b * Lc + par) * Hc + j] += hnew;
                }
            }
        }
    }
}

// ---------------------------------------------------------------------------
// output_t = outputs[b, root_index[b], :]
// ---------------------------------------------------------------------------
__global__ __launch_bounds__(256) void root_gather(
    const int* __restrict__ root_index, float* __restrict__ out)
{
    int i = blockIdx.x * 256 + threadIdx.x;   // over B*2H
    int b = i >> 10;
    int j = i & 1023;
    int r = root_index[b];
    out[(size_t)Bc * Lc * OUT2H + (size_t)b * OUT2H + j] =
        out[((size_t)b * Lc + r) * OUT2H + j];
}

// ---------------------------------------------------------------------------
extern "C" void kernel_launch(void* const* d_in, const int* in_sizes, int n_in,
                              void* d_out, int out_size)
{
    const float* emb       = (const float*)d_in[0];
    const int*   indexes   = (const int*)  d_in[1];
    /* child_mask d_in[2] unused: equivalent info in parent pointers */
    const int*   td_node   = (const int*)  d_in[3];
    const int*   td_pidx   = (const int*)  d_in[4];
    const float* td_pvalid = (const float*)d_in[5];
    const int*   root_idx  = (const int*)  d_in[6];
    const float* dt_Wx     = (const float*)d_in[7];
    const float* dt_Uh     = (const float*)d_in[8];
    const float* dt_b      = (const float*)d_in[9];
    const float* td_Wx     = (const float*)d_in[10];
    const float* td_Uh     = (const float*)d_in[11];
    const float* td_b      = (const float*)d_in[12];
    float* out = (float*)d_out;

    // 1) zero the child-sum accumulator (16.7M floats / 4 / 256 = 16384 blocks)
    zero_hsum_kernel<<<16384, 256>>>();

    // 2) precompute x-side gate preactivations for both passes
    xg_gemm<<<dim3(12, 256, 2), 256>>>(emb, dt_Wx, dt_b, td_Wx, td_b);

    // 3) 256 recurrence steps, DT and TD passes concurrent per launch
    for (int t = 0; t < Lc; t++) {
        step_kernel<<<dim3(8, 8, 2), 256>>>(t, indexes, td_node, td_pidx,
                                            td_pvalid, dt_Uh, td_Uh, out);
    }

    // 4) gather root hidden states into output_t
    root_gather<<<(Bc * OUT2H) / 256, 256>>>(root_idx, out);
}

// round 4
// speedup vs baseline: 1.8186x; 1.8186x over previous
#include <cuda_runtime.h>
#include <math.h>

#define Lc   256
#define Bc   128
#define Dc   512
#define Hc   512
#define G3c  1536      // 3*H
#define OUT2H 1024     // 2*H
#define MAXL 256
#define NROWS (Lc*Bc)  // 32768

// ------------------------- static device scratch ---------------------------
__device__ float g_xg[(size_t)2 * Lc * Bc * G3c];          // ~403 MB
__device__ float g_aprev[(size_t)2 * NROWS * Hc];          // ~134 MB assembled h_prev
__device__ int   g_lvl[2][Bc][Lc];
__device__ int   g_cnt[2][MAXL][Bc];
__device__ int   g_off[2][MAXL * Bc];                      // exclusive scan (lvl-major, b-minor)
__device__ int   g_lvloff[2][MAXL + 1];
__device__ int   g_rows[2][NROWS];                         // packed (b<<16)|node
__device__ int   g_nlvl[2];
__device__ int   g_nsteps;
__device__ int   g_choff[Bc][Lc + 1];
__device__ int   g_chlist[Bc][Lc];

// grid barrier state
__device__ volatile unsigned g_gen;
__device__ unsigned g_barcnt;

__device__ __forceinline__ void gridbar() {
    __syncthreads();
    if (threadIdx.x == 0) {
        unsigned gen = g_gen;
        __threadfence();
        unsigned old = atomicInc(&g_barcnt, gridDim.x - 1);
        if (old == gridDim.x - 1) {
            __threadfence();
            g_gen = gen + 1;
        } else {
            while (g_gen == gen) { __nanosleep(32); }
            __threadfence();
        }
    }
    __syncthreads();
}

// --------------------------- preprocessing ---------------------------------
__global__ __launch_bounds__(256) void Pzero() {
    int i = blockIdx.x * 256 + threadIdx.x;      // 65536 counters
    ((int*)g_cnt)[i] = 0;
    if (i == 0) { g_nlvl[0] = 0; g_nlvl[1] = 0; }
}

// one thread per batch: levels (DT height, TD depth), counts, child CSR
__global__ __launch_bounds__(128) void Plevels(const int* __restrict__ pidx) {
    int b = threadIdx.x;
    int lvl[Lc];
    // ---- DT (height): visit descending, relax parent ----
    for (int i = 0; i < Lc; i++) lvl[i] = 0;
    for (int i = Lc - 1; i >= 1; --i) {
        int p = pidx[i * Bc + b];
        int v = lvl[i] + 1;
        if (v > lvl[p]) lvl[p] = v;
        g_lvl[0][b][i] = lvl[i];
        g_cnt[0][lvl[i]][b]++;
    }
    g_lvl[0][b][0] = lvl[0];
    g_cnt[0][lvl[0]][b]++;
    atomicMax(&g_nlvl[0], lvl[0] + 1);
    // ---- TD (depth): visit ascending ----
    int d[Lc];
    d[0] = 0; g_lvl[1][b][0] = 0; g_cnt[1][0][b]++;
    int maxd = 0;
    for (int i = 1; i < Lc; ++i) {
        int p = pidx[i * Bc + b];
        d[i] = d[p] + 1;
        g_lvl[1][b][i] = d[i];
        g_cnt[1][d[i]][b]++;
        if (d[i] > maxd) maxd = d[i];
    }
    atomicMax(&g_nlvl[1], maxd + 1);
    // ---- child CSR (ascending child order: deterministic) ----
    int cnum[Lc], cur[Lc];
    for (int i = 0; i < Lc; i++) cnum[i] = 0;
    for (int i = 1; i < Lc; ++i) cnum[pidx[i * Bc + b]]++;
    int run = 0;
    g_choff[b][0] = 0;
    for (int p = 0; p < Lc; ++p) { run += cnum[p]; g_choff[b][p + 1] = run; cur[p] = 0; }
    for (int i = 1; i < Lc; ++i) {
        int p = pidx[i * Bc + b];
        g_chlist[b][g_choff[b][p] + cur[p]++] = i;
    }
}

// deterministic exclusive scan of counts -> offsets, level offsets, nsteps
__global__ __launch_bounds__(256) void Pscan() {
    __shared__ int part[256];
    int tid = threadIdx.x;
    for (int p = 0; p < 2; ++p) {
        const int* cnt = (const int*)g_cnt + p * (MAXL * Bc);
        int* off = (int*)g_off + p * (MAXL * Bc);
        int base = tid * 128, s = 0;
        for (int k = 0; k < 128; ++k) s += cnt[base + k];
        part[tid] = s;
        __syncthreads();
        if (tid == 0) {
            int run = 0;
            for (int t = 0; t < 256; ++t) { int v = part[t]; part[t] = run; run += v; }
        }
        __syncthreads();
        int run = part[tid];
        for (int k = 0; k < 128; ++k) {
            int idx = base + k;
            int v = cnt[idx];
            off[idx] = run;
            run += v;
        }
        __syncthreads();
        // level offsets
        for (int l = tid; l <= MAXL; l += 256)
            g_lvloff[p][l] = (l < MAXL) ? off[l * Bc] : NROWS;
        __syncthreads();
    }
    if (tid == 0) {
        int a = g_nlvl[0], c = g_nlvl[1];
        g_nsteps = a > c ? a : c;
    }
}

// deterministic scatter: thread = batch, walk nodes ascending
__global__ __launch_bounds__(128) void Pscatter() {
    int p = blockIdx.x;
    int b = threadIdx.x;
    int cur[MAXL];
    for (int l = 0; l < MAXL; ++l) cur[l] = 0;
    for (int i = 0; i < Lc; ++i) {
        int l = g_lvl[p][b][i];
        int pos = g_off[p][l * Bc + b] + cur[l]++;
        g_rows[p][pos] = (b << 16) | i;
    }
}

// ---------------------------------------------------------------------------
// Precompute XG = emb @ Wx + b for both passes (unchanged, works).
// ---------------------------------------------------------------------------
__global__ __launch_bounds__(256) void xg_gemm(
    const float* __restrict__ emb,
    const float* __restrict__ Wx0, const float* __restrict__ bias0,
    const float* __restrict__ Wx1, const float* __restrict__ bias1)
{
    const int pass = blockIdx.z;
    const float* __restrict__ Wx   = pass ? Wx1   : Wx0;
    const float* __restrict__ bias = pass ? bias1 : bias0;
    float* C = g_xg + (size_t)pass * Lc * Bc * G3c;

    __shared__ __align__(16) float As[16][128];
    __shared__ __align__(16) float Bs[16][128];

    const int m0 = blockIdx.y * 128;
    const int n0 = blockIdx.x * 128;
    const int tid = threadIdx.x;
    const int tr = tid >> 4;
    const int tc = tid & 15;

    float acc[8][8];
#pragma unroll
    for (int i = 0; i < 8; i++)
#pragma unroll
        for (int j = 0; j < 8; j++) acc[i][j] = 0.f;

    for (int kt = 0; kt < Dc; kt += 16) {
#pragma unroll
        for (int l = 0; l < 2; l++) {
            int f = tid + l * 256;
            int row = f >> 2;
            int c4 = (f & 3) << 2;
            float4 v = *(const float4*)&emb[(size_t)(m0 + row) * Dc + kt + c4];
            As[c4 + 0][row] = v.x;
            As[c4 + 1][row] = v.y;
            As[c4 + 2][row] = v.z;
            As[c4 + 3][row] = v.w;
        }
#pragma unroll
        for (int l = 0; l < 2; l++) {
            int f = tid + l * 256;
            int row = f >> 5;
            int c4 = (f & 31) << 2;
            *(float4*)&Bs[row][c4] =
                *(const float4*)&Wx[(size_t)(kt + row) * G3c + n0 + c4];
        }
        __syncthreads();
#pragma unroll
        for (int k = 0; k < 16; k++) {
            float a[8], b[8];
            *(float4*)&a[0] = *(const float4*)&As[k][tr * 8];
            *(float4*)&a[4] = *(const float4*)&As[k][tr * 8 + 4];
            *(float4*)&b[0] = *(const float4*)&Bs[k][tc * 8];
            *(float4*)&b[4] = *(const float4*)&Bs[k][tc * 8 + 4];
#pragma unroll
            for (int i = 0; i < 8; i++)
#pragma unroll
                for (int j = 0; j < 8; j++)
                    acc[i][j] += a[i] * b[j];
        }
        __syncthreads();
    }

#pragma unroll
    for (int i = 0; i < 8; i++) {
        int row = m0 + tr * 8 + i;
#pragma unroll
        for (int j = 0; j < 8; j += 4) {
            int col = n0 + tc * 8 + j;
            float4 v;
            v.x = acc[i][j + 0] + bias[col + 0];
            v.y = acc[i][j + 1] + bias[col + 1];
            v.z = acc[i][j + 2] + bias[col + 2];
            v.w = acc[i][j + 3] + bias[col + 3];
            *(float4*)&C[(size_t)row * G3c + col] = v;
        }
    }
}

// ---------------------------------------------------------------------------
// Persistent wavefront kernel: loop over levels; per level:
//   phase A: assemble h_prev rows into g_aprev (DT child-sum / TD parent copy)
//   phase B: GEMM tiles 64 rows x (64 j x 3 gates), K=512, fused GRU epilogue
// ---------------------------------------------------------------------------
__global__ __launch_bounds__(256, 2) void mega(
    const int* __restrict__ pidx, const float* __restrict__ pvalid,
    const float* __restrict__ Uh0, const float* __restrict__ Uh1,
    float* __restrict__ out)
{
    __shared__ __align__(16) float As[16][68];
    __shared__ __align__(16) float Bs[16][196];

    const int tid = threadIdx.x;
    const int tr = tid >> 4, tc = tid & 15;
    const int nsteps = g_nsteps;

    for (int l = 0; l < nsteps; ++l) {
        const int s0 = g_lvloff[0][l], e0 = g_lvloff[0][l + 1];
        const int s1 = g_lvloff[1][l], e1 = g_lvloff[1][l + 1];
        const int n0 = e0 - s0, n1 = e1 - s1;

        // ---------------- phase A: assemble ----------------
        {
            int total = (n0 + n1) << 7;   // 128 float4 per row
            for (int u = blockIdx.x * 256 + tid; u < total; u += gridDim.x * 256) {
                int rl = u >> 7;
                int k4 = (u & 127) << 2;
                if (rl < n0) {
                    int pos = s0 + rl;
                    int pk = g_rows[0][pos];
                    int b = pk >> 16, node = pk & 0xffff;
                    float4 acc = make_float4(0.f, 0.f, 0.f, 0.f);
                    int cs = g_choff[b][node], ce = g_choff[b][node + 1];
                    for (int c = cs; c < ce; ++c) {
                        int ch = g_chlist[b][c];
                        float4 v = *(const float4*)&out[((size_t)(b * Lc + ch) << 10) + k4];
                        acc.x += v.x; acc.y += v.y; acc.z += v.z; acc.w += v.w;
                    }
                    *(float4*)&g_aprev[((size_t)pos << 9) + k4] = acc;
                } else {
                    int pos = s1 + (rl - n0);
                    int pk = g_rows[1][pos];
                    int b = pk >> 16, node = pk & 0xffff;
                    int par = pidx[node * Bc + b];
                    float v = pvalid[node * Bc + b];
                    float4 t = *(const float4*)&out[((size_t)(b * Lc + par) << 10) + 512 + k4];
                    float4 a = make_float4(t.x * v, t.y * v, t.z * v, t.w * v);
                    *(float4*)&g_aprev[((size_t)(NROWS + pos) << 9) + k4] = a;
                }
            }
        }
        gridbar();

        // ---------------- phase B: GEMM + epilogue ----------------
        {
            int nt0 = (n0 + 63) >> 6, nt1 = (n1 + 63) >> 6;
            int ttot = (nt0 + nt1) << 3;
            for (int t = blockIdx.x; t < ttot; t += gridDim.x) {
                int p, loc;
                if (t < (nt0 << 3)) { p = 0; loc = t; }
                else                { p = 1; loc = t - (nt0 << 3); }
                int rowtile = loc >> 3, jt = loc & 7;
                int s = p ? s1 : s0;
                int n = p ? n1 : n0;
                int r0 = rowtile << 6;
                int nr = n - r0; if (nr > 64) nr = 64;
                int j0 = jt << 6;
                const float* __restrict__ Uh = p ? Uh1 : Uh0;
                const float* Abase = g_aprev + ((size_t)(p * NROWS + s + r0)) * Hc;

                float acc[4][4][3];
#pragma unroll
                for (int i = 0; i < 4; i++)
#pragma unroll
                    for (int j = 0; j < 4; j++)
#pragma unroll
                        for (int g = 0; g < 3; g++) acc[i][j][g] = 0.f;

                const int arow = tid >> 2;              // 0..63
                const int akq = (tid & 3) << 2;         // 0,4,8,12
                const int arow_eff = (arow < nr) ? arow : (nr - 1);

                for (int kc = 0; kc < Hc; kc += 16) {
                    float4 av = *(const float4*)&Abase[(size_t)arow_eff * Hc + kc + akq];
                    As[akq + 0][arow] = av.x;
                    As[akq + 1][arow] = av.y;
                    As[akq + 2][arow] = av.z;
                    As[akq + 3][arow] = av.w;
#pragma unroll
                    for (int lb = 0; lb < 3; ++lb) {
                        int f = tid + (lb << 8);
                        int kk = f / 48;
                        int c4 = (f - kk * 48) << 2;       // 0..188
                        int gate = c4 >> 6;
                        int j = c4 & 63;
                        *(float4*)&Bs[kk][c4] =
                            *(const float4*)&Uh[(size_t)(kc + kk) * G3c + gate * Hc + j0 + j];
                    }
                    __syncthreads();
#pragma unroll
                    for (int k = 0; k < 16; ++k) {
                        float4 a4 = *(const float4*)&As[k][tr << 2];
                        float4 b0 = *(const float4*)&Bs[k][(tc << 2)];
                        float4 b1 = *(const float4*)&Bs[k][64 + (tc << 2)];
                        float4 b2 = *(const float4*)&Bs[k][128 + (tc << 2)];
                        const float a[4]  = {a4.x, a4.y, a4.z, a4.w};
                        const float v0[4] = {b0.x, b0.y, b0.z, b0.w};
                        const float v1[4] = {b1.x, b1.y, b1.z, b1.w};
                        const float v2[4] = {b2.x, b2.y, b2.z, b2.w};
#pragma unroll
                        for (int i = 0; i < 4; i++)
#pragma unroll
                            for (int j = 0; j < 4; j++) {
                                acc[i][j][0] += a[i] * v0[j];
                                acc[i][j][1] += a[i] * v1[j];
                                acc[i][j][2] += a[i] * v2[j];
                            }
                    }
                    __syncthreads();
                }

                // fused GRU epilogue
#pragma unroll
                for (int i = 0; i < 4; ++i) {
                    int rloc = (tr << 2) + i;
                    if (rloc < nr) {
                        int pos = s + r0 + rloc;
                        int pk = g_rows[p][pos];
                        int b = pk >> 16, node = pk & 0xffff;
                        const float* xrow =
                            g_xg + ((size_t)(p * Lc + node) * Bc + b) * G3c + j0;
                        const float* hrow =
                            g_aprev + ((size_t)(p * NROWS + pos) << 9) + j0;
                        float* orow =
                            out + ((size_t)(b * Lc + node) << 10) + (p << 9) + j0;
#pragma unroll
                        for (int jj = 0; jj < 4; ++jj) {
                            int j = (tc << 2) + jj;
                            float xr = xrow[j];
                            float xz = xrow[Hc + j];
                            float xn = xrow[2 * Hc + j];
                            float hp = hrow[j];
                            float r = 1.f / (1.f + expf(-(xr + acc[i][jj][0])));
                            float z = 1.f / (1.f + expf(-(xz + acc[i][jj][1])));
                            float nn = tanhf(xn + r * acc[i][jj][2]);
                            orow[j] = (1.f - z) * nn + z * hp;
                        }
                    }
                }
            }
        }
        gridbar();
    }
}

// ---------------------------------------------------------------------------
__global__ __launch_bounds__(256) void root_gather(
    const int* __restrict__ root_index, float* __restrict__ out)
{
    int i = blockIdx.x * 256 + threadIdx.x;   // over B*2H
    int b = i >> 10;
    int j = i & 1023;
    int r = root_index[b];
    out[(size_t)Bc * Lc * OUT2H + (size_t)b * OUT2H + j] =
        out[((size_t)b * Lc + r) * OUT2H + j];
}

// ---------------------------------------------------------------------------
extern "C" void kernel_launch(void* const* d_in, const int* in_sizes, int n_in,
                              void* d_out, int out_size)
{
    const float* emb       = (const float*)d_in[0];
    /* indexes d_in[1] unused; child_mask d_in[2] unused */
    const int*   td_pidx   = (const int*)  d_in[4];
    const float* td_pvalid = (const float*)d_in[5];
    const int*   root_idx  = (const int*)  d_in[6];
    const float* dt_Wx     = (const float*)d_in[7];
    const float* dt_Uh     = (const float*)d_in[8];
    const float* dt_b      = (const float*)d_in[9];
    const float* td_Wx     = (const float*)d_in[10];
    const float* td_Uh     = (const float*)d_in[11];
    const float* td_b      = (const float*)d_in[12];
    float* out = (float*)d_out;

    int sms = 148;
    cudaDeviceGetAttribute(&sms, cudaDevAttrMultiProcessorCount, 0);
    int NB = sms * 2;   // must match __launch_bounds__(256,2) residency

    // x-side gate preactivations (independent of recurrence)
    xg_gemm<<<dim3(12, 256, 2), 256>>>(emb, dt_Wx, dt_b, td_Wx, td_b);

    // level preprocessing (deterministic)
    Pzero<<<256, 256>>>();
    Plevels<<<1, 128>>>(td_pidx);
    Pscan<<<1, 256>>>();
    Pscatter<<<2, 128>>>();

    // wavefront recurrence (both passes), persistent grid with barriers
    mega<<<NB, 256>>>(td_pidx, td_pvalid, dt_Uh, td_Uh, out);

    // output_t = outputs[b, root, :]
    root_gather<<<(Bc * OUT2H) / 256, 256>>>(root_idx, out);
}

// round 5
// speedup vs baseline: 3.3859x; 1.8618x over previous
#include <cuda_runtime.h>
#include <math.h>

#define Lc   256
#define Bc   128
#define Dc   512
#define Hc   512
#define G3c  1536      // 3*H
#define OUT2H 1024     // 2*H
#define MAXL 256
#define NROWS (Lc*Bc)  // 32768

// ------------------------- static device scratch ---------------------------
__device__ float g_xg[(size_t)2 * Lc * Bc * G3c];          // ~403 MB
__device__ float g_aprev[(size_t)NROWS * Hc];              // DT child sums
__device__ int   g_lvl[2][Bc][Lc];
__device__ int   g_cnt[2][MAXL][Bc];
__device__ int   g_off[2][MAXL * Bc];
__device__ int   g_lvloff[2][MAXL + 1];
__device__ int   g_rows[2][NROWS];                         // (b<<16)|node
__device__ int   g_nlvl[2];
__device__ int   g_nsteps;
__device__ int   g_choff[Bc][Lc + 1];
__device__ int   g_chlist[Bc][Lc];

__device__ volatile unsigned g_gen;
__device__ unsigned g_barcnt;

__device__ __forceinline__ void gridbar() {
    __syncthreads();
    if (threadIdx.x == 0) {
        unsigned gen = g_gen;
        __threadfence();
        unsigned old = atomicInc(&g_barcnt, gridDim.x - 1);
        if (old == gridDim.x - 1) {
            __threadfence();
            g_gen = gen + 1;
        } else {
            while (g_gen == gen) { __nanosleep(32); }
            __threadfence();
        }
    }
    __syncthreads();
}

// ------------------------- tf32 mma helpers --------------------------------
__device__ __forceinline__ unsigned cvt_tf32(float x) {
    unsigned u; asm("cvt.rna.tf32.f32 %0, %1;" : "=r"(u) : "f"(x)); return u;
}
__device__ __forceinline__ void mma8(float* c, const unsigned* a, const unsigned* b) {
    asm volatile(
        "mma.sync.aligned.m16n8k8.row.col.f32.tf32.tf32.f32 "
        "{%0,%1,%2,%3},{%4,%5,%6,%7},{%8,%9},{%0,%1,%2,%3};\n"
        : "+f"(c[0]), "+f"(c[1]), "+f"(c[2]), "+f"(c[3])
        : "r"(a[0]), "r"(a[1]), "r"(a[2]), "r"(a[3]), "r"(b[0]), "r"(b[1]));
}
__device__ __forceinline__ float sigf(float x) {
    return 1.f / (1.f + __expf(-x));
}
__device__ __forceinline__ float tanhfast(float x) {
    return 2.f * sigf(2.f * x) - 1.f;
}

// --------------------------- preprocessing ---------------------------------
// one block per tree: depths (pointer jumping), heights (serial, smem),
// per-level counts, child CSR (deterministic ascending order)
__global__ __launch_bounds__(256) void Pprep(const int* __restrict__ pidx) {
    __shared__ int par[256], anc[256], dst[256], hgt[256];
    __shared__ int c0[256], c1[256], tmpc[256], cur[256], loff[257];
    __shared__ int mxd;
    const int b = blockIdx.x, i = threadIdx.x;
    par[i] = (i == 0) ? 0 : pidx[i * Bc + b];
    c0[i] = 0; c1[i] = 0; tmpc[i] = 0; hgt[i] = 0;
    if (i == 0) mxd = 0;
    __syncthreads();
    anc[i] = par[i];
    dst[i] = (i == 0) ? 0 : 1;
    __syncthreads();
#pragma unroll
    for (int r = 0; r < 8; ++r) {
        int a = anc[i];
        int nd = dst[i] + dst[a];
        int na = anc[a];
        __syncthreads();
        dst[i] = nd; anc[i] = na;
        __syncthreads();
    }
    const int depth = dst[i];
    atomicMax(&mxd, depth);
    if (i == 0) {
        for (int j = 255; j >= 1; --j) {
            int p = par[j], v = hgt[j] + 1;
            if (v > hgt[p]) hgt[p] = v;
        }
    }
    __syncthreads();
    const int h = hgt[i];
    atomicAdd(&c0[h], 1);
    atomicAdd(&c1[depth], 1);
    g_lvl[0][b][i] = h;
    g_lvl[1][b][i] = depth;
    if (i > 0) atomicAdd(&tmpc[par[i]], 1);
    __syncthreads();
    g_cnt[0][i][b] = c0[i];
    g_cnt[1][i][b] = c1[i];
    if (i == 0) {
        atomicMax(&g_nlvl[0], hgt[0] + 1);
        atomicMax(&g_nlvl[1], mxd + 1);
        int run = 0;
        loff[0] = 0;
        for (int p2 = 0; p2 < Lc; ++p2) {
            run += tmpc[p2]; loff[p2 + 1] = run; cur[p2] = 0;
        }
        for (int j = 1; j < Lc; ++j) {
            int p2 = par[j];
            g_chlist[b][loff[p2] + cur[p2]++] = j;
        }
    }
    __syncthreads();
    g_choff[b][i] = loff[i];
    if (i == 0) g_choff[b][Lc] = loff[Lc];
}

// global exclusive scan of counts (32768 per pass), level offsets, nsteps
__global__ __launch_bounds__(1024) void Pscan2() {
    __shared__ int wsum[32];
    const int tid = threadIdx.x;
    const int lane = tid & 31, wid = tid >> 5;
    for (int p = 0; p < 2; ++p) {
        const int* cnt = &g_cnt[p][0][0];
        int* off = &g_off[p][0];
        const int base = tid * 32;
        int s = 0;
#pragma unroll
        for (int k = 0; k < 32; ++k) s += cnt[base + k];
        int v = s;
#pragma unroll
        for (int d = 1; d < 32; d <<= 1) {
            int t2 = __shfl_up_sync(0xffffffffu, v, d);
            if (lane >= d) v += t2;
        }
        if (lane == 31) wsum[wid] = v;
        __syncthreads();
        if (wid == 0) {
            int w = wsum[lane];
#pragma unroll
            for (int d = 1; d < 32; d <<= 1) {
                int t2 = __shfl_up_sync(0xffffffffu, w, d);
                if (lane >= d) w += t2;
            }
            wsum[lane] = w;
        }
        __syncthreads();
        int run = v - s + (wid ? wsum[wid - 1] : 0);
#pragma unroll
        for (int k = 0; k < 32; ++k) { off[base + k] = run; run += cnt[base + k]; }
        __syncthreads();
        for (int l2 = tid; l2 < MAXL; l2 += 1024) g_lvloff[p][l2] = off[l2 * Bc];
        if (tid == 0) g_lvloff[p][MAXL] = NROWS;
        __syncthreads();
    }
    if (tid == 0) {
        int a = g_nlvl[0], c = g_nlvl[1];
        g_nsteps = a > c ? a : c;
    }
}

// deterministic scatter; one block per (pass, tree), smem-staged
__global__ __launch_bounds__(256) void Pscatter2() {
    __shared__ int cur[256], lv[256], lo[256];
    const int p = blockIdx.x >> 7, b = blockIdx.x & 127;
    const int i = threadIdx.x;
    cur[i] = 0;
    lv[i] = g_lvl[p][b][i];
    lo[i] = g_off[p][i * Bc + b];
    __syncthreads();
    if (i == 0) {
        for (int j = 0; j < Lc; ++j) {
            int l = lv[j];
            g_rows[p][lo[l] + cur[l]++] = (b << 16) | j;
        }
    }
}

// ---------------------------------------------------------------------------
// XG = emb @ Wx + b (tf32 tensor cores). 128x128x32 tiles, 256 thr = 2x4 warps,
// warp tile 64x32. grid (12, 256, 2).
// ---------------------------------------------------------------------------
__global__ __launch_bounds__(256, 2) void xg_gemm_t(
    const float* __restrict__ emb,
    const float* __restrict__ Wx0, const float* __restrict__ bias0,
    const float* __restrict__ Wx1, const float* __restrict__ bias1)
{
    const int pass = blockIdx.z;
    const float* __restrict__ Wx   = pass ? Wx1   : Wx0;
    const float* __restrict__ bias = pass ? bias1 : bias0;
    float* C = g_xg + (size_t)pass * Lc * Bc * G3c;

    __shared__ unsigned As[128][36];   // [m][k], pad 4
    __shared__ unsigned Bs[32][136];   // [k][n], pad 8

    const int m0 = blockIdx.y * 128;
    const int n0b = blockIdx.x * 128;
    const int tid = threadIdx.x;
    const int lane = tid & 31, wid = tid >> 5;
    const int g = lane >> 2, tg = lane & 3;
    const int wm = wid >> 2, wn = wid & 3;

    float acc[4][4][4];
#pragma unroll
    for (int mi = 0; mi < 4; mi++)
#pragma unroll
        for (int ni = 0; ni < 4; ni++)
#pragma unroll
            for (int q = 0; q < 4; q++) acc[mi][ni][q] = 0.f;

    for (int kc = 0; kc < Dc; kc += 32) {
#pragma unroll
        for (int l2 = 0; l2 < 4; ++l2) {
            int flat = tid + (l2 << 8);           // 1024 float4 slots
            int row = flat >> 3, c4 = (flat & 7) << 2;
            float4 v = *(const float4*)&emb[(size_t)(m0 + row) * Dc + kc + c4];
            uint4 u;
            u.x = cvt_tf32(v.x); u.y = cvt_tf32(v.y);
            u.z = cvt_tf32(v.z); u.w = cvt_tf32(v.w);
            *(uint4*)&As[row][c4] = u;
        }
#pragma unroll
        for (int l2 = 0; l2 < 4; ++l2) {
            int flat = tid + (l2 << 8);           // 1024 float4 slots
            int kk = flat >> 5, c4 = (flat & 31) << 2;
            float4 v = *(const float4*)&Wx[(size_t)(kc + kk) * G3c + n0b + c4];
            uint4 u;
            u.x = cvt_tf32(v.x); u.y = cvt_tf32(v.y);
            u.z = cvt_tf32(v.z); u.w = cvt_tf32(v.w);
            *(uint4*)&Bs[kk][c4] = u;
        }
        __syncthreads();
#pragma unroll
        for (int kk = 0; kk < 32; kk += 8) {
            unsigned af[4][4], bf[4][2];
#pragma unroll
            for (int mi = 0; mi < 4; ++mi) {
                int m = wm * 64 + mi * 16;
                af[mi][0] = As[m + g][kk + tg];
                af[mi][1] = As[m + g + 8][kk + tg];
                af[mi][2] = As[m + g][kk + tg + 4];
                af[mi][3] = As[m + g + 8][kk + tg + 4];
            }
#pragma unroll
            for (int ni = 0; ni < 4; ++ni) {
                int nn = wn * 32 + ni * 8 + g;
                bf[ni][0] = Bs[kk + tg][nn];
                bf[ni][1] = Bs[kk + tg + 4][nn];
            }
#pragma unroll
            for (int mi = 0; mi < 4; ++mi)
#pragma unroll
                for (int ni = 0; ni < 4; ++ni)
                    mma8(acc[mi][ni], af[mi], bf[ni]);
        }
        __syncthreads();
    }

#pragma unroll
    for (int mi = 0; mi < 4; ++mi)
#pragma unroll
        for (int ni = 0; ni < 4; ++ni) {
            int row = m0 + wm * 64 + mi * 16 + g;
            int col = n0b + wn * 32 + ni * 8 + 2 * tg;
            float b0v = bias[col], b1v = bias[col + 1];
            C[(size_t)row * G3c + col]           = acc[mi][ni][0] + b0v;
            C[(size_t)row * G3c + col + 1]       = acc[mi][ni][1] + b1v;
            C[(size_t)(row + 8) * G3c + col]     = acc[mi][ni][2] + b0v;
            C[(size_t)(row + 8) * G3c + col + 1] = acc[mi][ni][3] + b1v;
        }
}

// ---------------------------------------------------------------------------
// Persistent wavefront kernel (tf32 tensor cores).
// Phase A: DT child-sums into g_aprev. Phase B: per tile (64 rows x 64 j x 3
// gates) GEMM h_prev @ Uh with TD rows gathered inline from out, C staged
// through smem, fused GRU epilogue.
// ---------------------------------------------------------------------------
__global__ __launch_bounds__(256, 2) void mega(
    const int* __restrict__ pidx, const float* __restrict__ pvalid,
    const float* __restrict__ Uh0, const float* __restrict__ Uh1,
    float* __restrict__ out)
{
    __shared__ union {
        struct { unsigned A[64][36]; unsigned B[32][200]; } g;  // 34816 B
        float C[32][196];                                       // 25088 B
    } su;
    __shared__ const float* rptr[64];
    __shared__ float rsc[64];
    __shared__ int rpk[64];

    const int tid = threadIdx.x;
    const int lane = tid & 31, wid = tid >> 5;
    const int g = lane >> 2, tg = lane & 3;
    const int wm = wid >> 2, wn = wid & 3;      // 2 x 4 warps
    const int nsteps = g_nsteps;

    for (int l = 0; l < nsteps; ++l) {
        const int s0 = g_lvloff[0][l], e0 = g_lvloff[0][l + 1];
        const int s1 = g_lvloff[1][l], e1 = g_lvloff[1][l + 1];
        const int n0 = e0 - s0, n1 = e1 - s1;

        // ---- phase A: DT child-sum assembly ----
        {
            int total = n0 << 7;   // 128 float4 per row
            for (int u = blockIdx.x * 256 + tid; u < total; u += gridDim.x * 256) {
                int rl = u >> 7, k4 = (u & 127) << 2;
                int pos = s0 + rl;
                int pk = g_rows[0][pos];
                int b = pk >> 16, node = pk & 0xffff;
                float4 a4 = make_float4(0.f, 0.f, 0.f, 0.f);
                int cs = g_choff[b][node], ce = g_choff[b][node + 1];
                for (int c = cs; c < ce; ++c) {
                    int ch = g_chlist[b][c];
                    float4 v = *(const float4*)&out[((size_t)(b * Lc + ch) << 10) + k4];
                    a4.x += v.x; a4.y += v.y; a4.z += v.z; a4.w += v.w;
                }
                *(float4*)&g_aprev[((size_t)pos << 9) + k4] = a4;
            }
        }
        gridbar();

        // ---- phase B: GEMM + fused epilogue ----
        {
            const int nt0 = (n0 + 63) >> 6, nt1 = (n1 + 63) >> 6;
            const int ttot = (nt0 + nt1) << 3;
            for (int t = blockIdx.x; t < ttot; t += gridDim.x) {
                const int p = (t >= (nt0 << 3)) ? 1 : 0;
                const int loc = p ? (t - (nt0 << 3)) : t;
                const int rowtile = loc >> 3, jt = loc & 7;
                const int s = p ? s1 : s0;
                const int n = p ? n1 : n0;
                const int r0 = rowtile << 6;
                int nr = n - r0; if (nr > 64) nr = 64;
                const int j0 = jt << 6;
                const float* __restrict__ Uh = p ? Uh1 : Uh0;

                __syncthreads();
                if (tid < 64) {
                    int rloc = tid < nr ? tid : (nr - 1);
                    int pos = s + r0 + rloc;
                    int pk = g_rows[p][pos];
                    rpk[tid] = pk;
                    int b = pk >> 16, node = pk & 0xffff;
                    if (p == 0) {
                        rptr[tid] = g_aprev + ((size_t)pos << 9);
                        rsc[tid] = 1.f;
                    } else {
                        int par = pidx[node * Bc + b];
                        rptr[tid] = out + ((size_t)(b * Lc + par) << 10) + Hc;
                        rsc[tid] = pvalid[node * Bc + b];
                    }
                }
                __syncthreads();

                float acc[2][6][4];
#pragma unroll
                for (int mi = 0; mi < 2; mi++)
#pragma unroll
                    for (int ni = 0; ni < 6; ni++)
#pragma unroll
                        for (int q = 0; q < 4; q++) acc[mi][ni][q] = 0.f;

                for (int kc = 0; kc < Hc; kc += 32) {
#pragma unroll
                    for (int l2 = 0; l2 < 2; ++l2) {          // A: 512 f4 slots
                        int flat = tid + (l2 << 8);
                        int row = flat >> 3, c4 = (flat & 7) << 2;
                        float4 v = *(const float4*)(rptr[row] + kc + c4);
                        float sc = rsc[row];
                        uint4 u;
                        u.x = cvt_tf32(v.x * sc); u.y = cvt_tf32(v.y * sc);
                        u.z = cvt_tf32(v.z * sc); u.w = cvt_tf32(v.w * sc);
                        *(uint4*)&su.g.A[row][c4] = u;
                    }
#pragma unroll
                    for (int l2 = 0; l2 < 6; ++l2) {          // B: 1536 f4 slots
                        int flat = tid + (l2 << 8);
                        int kk = flat / 48;
                        int c4 = (flat - kk * 48) << 2;       // 0..188
                        int gate = c4 >> 6, j = c4 & 63;
                        float4 v = *(const float4*)&Uh[(size_t)(kc + kk) * G3c +
                                                       gate * Hc + j0 + j];
                        uint4 u;
                        u.x = cvt_tf32(v.x); u.y = cvt_tf32(v.y);
                        u.z = cvt_tf32(v.z); u.w = cvt_tf32(v.w);
                        *(uint4*)&su.g.B[kk][c4] = u;
                    }
                    __syncthreads();
#pragma unroll
                    for (int kk = 0; kk < 32; kk += 8) {
                        unsigned af[2][4], bf[6][2];
#pragma unroll
                        for (int mi = 0; mi < 2; ++mi) {
                            int m = wm * 32 + mi * 16;
                            af[mi][0] = su.g.A[m + g][kk + tg];
                            af[mi][1] = su.g.A[m + g + 8][kk + tg];
                            af[mi][2] = su.g.A[m + g][kk + tg + 4];
                            af[mi][3] = su.g.A[m + g + 8][kk + tg + 4];
                        }
#pragma unroll
                        for (int ni = 0; ni < 6; ++ni) {
                            int nn = wn * 48 + ni * 8 + g;
                            bf[ni][0] = su.g.B[kk + tg][nn];
                            bf[ni][1] = su.g.B[kk + tg + 4][nn];
                        }
#pragma unroll
                        for (int mi = 0; mi < 2; ++mi)
#pragma unroll
                            for (int ni = 0; ni < 6; ++ni)
                                mma8(acc[mi][ni], af[mi], bf[ni]);
                    }
                    __syncthreads();
                }

                // epilogue via staged C, two 32-row halves
#pragma unroll
                for (int half = 0; half < 2; ++half) {
                    if (wm == half) {
#pragma unroll
                        for (int mi = 0; mi < 2; ++mi)
#pragma unroll
                            for (int ni = 0; ni < 6; ++ni) {
                                int r = mi * 16 + g;
                                int c = wn * 48 + ni * 8 + 2 * tg;
                                su.C[r][c]         = acc[mi][ni][0];
                                su.C[r][c + 1]     = acc[mi][ni][1];
                                su.C[r + 8][c]     = acc[mi][ni][2];
                                su.C[r + 8][c + 1] = acc[mi][ni][3];
                            }
                    }
                    __syncthreads();
#pragma unroll
                    for (int l2 = 0; l2 < 8; ++l2) {
                        int flat = tid + (l2 << 8);           // 2048 outputs
                        int rl = flat >> 6, j = flat & 63;
                        int rloc = half * 32 + rl;
                        if (rloc < nr) {
                            int pk = rpk[rloc];
                            int b = pk >> 16, node = pk & 0xffff;
                            const float* xrow = g_xg +
                                ((size_t)((p * Lc + node) * Bc + b)) * G3c + j0;
                            float hr = su.C[rl][j];
                            float hz = su.C[rl][64 + j];
                            float hg = su.C[rl][128 + j];
                            float hp = rptr[rloc][j0 + j] * rsc[rloc];
                            float r = sigf(xrow[j] + hr);
                            float z = sigf(xrow[Hc + j] + hz);
                            float nn2 = tanhfast(xrow[2 * Hc + j] + r * hg);
                            out[((size_t)(b * Lc + node) << 10) + (p << 9) + j0 + j] =
                                (1.f - z) * nn2 + z * hp;
                        }
                    }
                    __syncthreads();
                }
            }
        }
        gridbar();
    }
}

// ---------------------------------------------------------------------------
__global__ __launch_bounds__(256) void root_gather(
    const int* __restrict__ root_index, float* __restrict__ out)
{
    int i = blockIdx.x * 256 + threadIdx.x;   // over B*2H
    int b = i >> 10;
    int j = i & 1023;
    int r = root_index[b];
    out[(size_t)Bc * Lc * OUT2H + (size_t)b * OUT2H + j] =
        out[((size_t)b * Lc + r) * OUT2H + j];
}

// ---------------------------------------------------------------------------
extern "C" void kernel_launch(void* const* d_in, const int* in_sizes, int n_in,
                              void* d_out, int out_size)
{
    const float* emb       = (const float*)d_in[0];
    /* indexes d_in[1], child_mask d_in[2] unused (parent pointers suffice) */
    const int*   td_pidx   = (const int*)  d_in[4];
    const float* td_pvalid = (const float*)d_in[5];
    const int*   root_idx  = (const int*)  d_in[6];
    const float* dt_Wx     = (const float*)d_in[7];
    const float* dt_Uh     = (const float*)d_in[8];
    const float* dt_b      = (const float*)d_in[9];
    const float* td_Wx     = (const float*)d_in[10];
    const float* td_Uh     = (const float*)d_in[11];
    const float* td_b      = (const float*)d_in[12];
    float* out = (float*)d_out;

    int sms = 148;
    cudaDeviceGetAttribute(&sms, cudaDevAttrMultiProcessorCount, 0);
    int NB = sms * 2;   // matches __launch_bounds__(256,2) residency

    // x-side gate preactivations (tf32 tensor cores)
    xg_gemm_t<<<dim3(12, 256, 2), 256>>>(emb, dt_Wx, dt_b, td_Wx, td_b);

    // level preprocessing (deterministic)
    Pprep<<<128, 256>>>(td_pidx);
    Pscan2<<<1, 1024>>>();
    Pscatter2<<<256, 256>>>();

    // wavefront recurrence (both passes), persistent grid with barriers
    mega<<<NB, 256>>>(td_pidx, td_pvalid, dt_Uh, td_Uh, out);

    // output_t = outputs[b, root, :]
    root_gather<<<(Bc * OUT2H) / 256, 256>>>(root_idx, out);
}